// round 8
// baseline (speedup 1.0000x reference)
#include <cuda_runtime.h>

#define BB 64
#define TT 2048
#define DD 512

// Scratch (allocation-free contract: __device__ globals)
__device__ float        g_phis[BB * DD];
__device__ float        g_v[BB * DD];
__device__ float        g_e[BB * TT];
__device__ float        g_hsum[BB * TT];
__device__ unsigned int g_Mbits[BB];     // order-encoded per-b score max

// Monotone order-preserving encode/decode: encode(x) < encode(y) <=> x < y
__device__ __forceinline__ unsigned int enc_f(float x) {
    unsigned int b = __float_as_uint(x);
    return (b & 0x80000000u) ? ~b : (b | 0x80000000u);
}
__device__ __forceinline__ float dec_f(unsigned int u) {
    return __uint_as_float((u & 0x80000000u) ? (u & 0x7fffffffu) : ~u);
}

// ---------------------------------------------------------------------------
// k_phis: phi_s[b,a] = dot(s[b,:], phi_w[a,:]) + phi_b[a]
// grid (32 a-tiles, 64 b) = 2048 blocks x 256 threads. Each warp does 2 a's.
// Block (0,0) also resets g_Mbits for this launch (runs before k_scores).
// ---------------------------------------------------------------------------
__global__ void k_phis(const float* __restrict__ s,
                       const float* __restrict__ phi_w,
                       const float* __restrict__ phi_b) {
    const int b    = blockIdx.y;
    const int tid  = threadIdx.x;          // 256
    const int lane = tid & 31;
    const int warp = tid >> 5;             // 8 warps

    if (blockIdx.x == 0 && blockIdx.y == 0 && tid < BB)
        g_Mbits[tid] = 0u;                 // encodes below any finite float

    __shared__ float sh_s[DD];
    sh_s[tid]       = s[(size_t)b * DD + tid];
    sh_s[tid + 256] = s[(size_t)b * DD + tid + 256];
    __syncthreads();
    const float4* s4 = (const float4*)sh_s;

    const int a0 = blockIdx.x * 16 + warp * 2;
    const int a1 = a0 + 1;
    const float4* w0 = (const float4*)(phi_w + (size_t)a0 * DD);
    const float4* w1 = (const float4*)(phi_w + (size_t)a1 * DD);

    float acc0 = 0.f, acc1 = 0.f;
    #pragma unroll
    for (int j = 0; j < 4; j++) {
        float4 wa = w0[lane + 32 * j];
        float4 wb = w1[lane + 32 * j];
        float4 sv = s4[lane + 32 * j];
        acc0 += wa.x * sv.x + wa.y * sv.y + wa.z * sv.z + wa.w * sv.w;
        acc1 += wb.x * sv.x + wb.y * sv.y + wb.z * sv.z + wb.w * sv.w;
    }
    #pragma unroll
    for (int off = 16; off; off >>= 1) {
        acc0 += __shfl_xor_sync(0xffffffffu, acc0, off);
        acc1 += __shfl_xor_sync(0xffffffffu, acc1, off);
    }
    if (lane == 0) {
        g_phis[b * DD + a0] = acc0 + phi_b[a0];
        g_phis[b * DD + a1] = acc1 + phi_b[a1];
    }
}

// ---------------------------------------------------------------------------
// k_v: v[b,k] = sum_a phi_s[b,a] * psi_w[a,k]
// grid (32 b-pairs, 4 k-slices) = 128 blocks x 512 threads (16 warps).
// psi_b dropped: softmax is shift-invariant to the per-b constant it adds.
// ---------------------------------------------------------------------------
__global__ void k_v(const float* __restrict__ psi_w) {
    const int b0   = blockIdx.x * 2;
    const int ks   = blockIdx.y;           // k-slice: 32 float4 columns
    const int tid  = threadIdx.x;          // 512
    const int lane = tid & 31;
    const int warp = tid >> 5;             // 16 warps

    __shared__ float  ph0[DD], ph1[DD];
    __shared__ float4 part0[16][32];
    __shared__ float4 part1[16][32];

    ph0[tid] = g_phis[(size_t)b0 * DD + tid];
    ph1[tid] = g_phis[(size_t)(b0 + 1) * DD + tid];
    __syncthreads();

    const float4* w4 = (const float4*)psi_w;     // [512][128] float4
    const int col = ks * 32 + lane;              // 0..127

    float4 acc0 = make_float4(0.f, 0.f, 0.f, 0.f);
    float4 acc1 = make_float4(0.f, 0.f, 0.f, 0.f);
    const int abase = warp * 32;
    #pragma unroll 8
    for (int i = 0; i < 32; i++) {
        const int a = abase + i;
        const float4 w = w4[(size_t)a * 128 + col];
        const float p0 = ph0[a], p1 = ph1[a];
        acc0.x += p0 * w.x; acc0.y += p0 * w.y;
        acc0.z += p0 * w.z; acc0.w += p0 * w.w;
        acc1.x += p1 * w.x; acc1.y += p1 * w.y;
        acc1.z += p1 * w.z; acc1.w += p1 * w.w;
    }
    part0[warp][lane] = acc0;
    part1[warp][lane] = acc1;
    __syncthreads();

    if (warp == 0) {
        float4 r = part0[0][lane];
        #pragma unroll
        for (int w = 1; w < 16; w++) {
            float4 p = part0[w][lane];
            r.x += p.x; r.y += p.y; r.z += p.z; r.w += p.w;
        }
        ((float4*)g_v)[(size_t)b0 * 128 + col] = r;
    } else if (warp == 1) {
        float4 r = part1[0][lane];
        #pragma unroll
        for (int w = 1; w < 16; w++) {
            float4 p = part1[w][lane];
            r.x += p.x; r.y += p.y; r.z += p.z; r.w += p.w;
        }
        ((float4*)g_v)[(size_t)(b0 + 1) * 128 + col] = r;
    }
}

// ---------------------------------------------------------------------------
// k_scores: the DRAM-bound pass (one 268 MB streaming read of h).
// grid 8192 x 256, __launch_bounds__(256,4): 4 CTAs/SM = 32 warps/SM.
// v staged via smem once per block, pinned in 16 regs/warp.
// h loads use __ldcs (evict-first): zero reuse -> keep it out of L2.
// Lane 0 additionally folds the per-b score max into g_Mbits via atomicMax
// (order-encoded uint; idempotent across graph replays).
// ---------------------------------------------------------------------------
__global__ void __launch_bounds__(256, 4) k_scores(const float* __restrict__ h) {
    const int tid  = threadIdx.x;
    const int lane = tid & 31;
    const int warp = tid >> 5;
    const int row0 = blockIdx.x * 16 + warp * 2;
    const int b    = blockIdx.x >> 7;      // 128 blocks per b

    __shared__ float sh_v[DD];
    ((float2*)sh_v)[tid] = ((const float2*)(g_v + (size_t)b * DD))[tid];
    __syncthreads();

    const float4* sv4 = (const float4*)sh_v;
    float4 v[4];
    #pragma unroll
    for (int j = 0; j < 4; j++) v[j] = sv4[lane + 32 * j];

    const float4* ha = (const float4*)(h + (size_t)row0 * DD);
    const float4* hb = ha + 128;
    float4 A[4], B[4];
    #pragma unroll
    for (int j = 0; j < 4; j++) A[j] = __ldcs(&ha[lane + 32 * j]);
    #pragma unroll
    for (int j = 0; j < 4; j++) B[j] = __ldcs(&hb[lane + 32 * j]);

    float e0 = 0.f, s0 = 0.f, e1 = 0.f, s1 = 0.f;
    #pragma unroll
    for (int j = 0; j < 4; j++) {
        e0 += A[j].x * v[j].x + A[j].y * v[j].y + A[j].z * v[j].z + A[j].w * v[j].w;
        s0 += (A[j].x + A[j].y) + (A[j].z + A[j].w);
        e1 += B[j].x * v[j].x + B[j].y * v[j].y + B[j].z * v[j].z + B[j].w * v[j].w;
        s1 += (B[j].x + B[j].y) + (B[j].z + B[j].w);
    }
    #pragma unroll
    for (int off = 16; off; off >>= 1) {
        e0 += __shfl_xor_sync(0xffffffffu, e0, off);
        s0 += __shfl_xor_sync(0xffffffffu, s0, off);
        e1 += __shfl_xor_sync(0xffffffffu, e1, off);
        s1 += __shfl_xor_sync(0xffffffffu, s1, off);
    }
    if (lane == 0) {
        *(float2*)(g_e    + row0) = make_float2(e0, e1);
        *(float2*)(g_hsum + row0) = make_float2(s0, s1);
        atomicMax(&g_Mbits[b], enc_f(fmaxf(e0, e1)));
    }
}

// ---------------------------------------------------------------------------
// k_softmax: per-b sum of exp(e-M) (M precomputed by k_scores atomics),
// then out = exp(e-M)/S * hsum. ONE block-reduction round only.
// 64 blocks x 1024 threads, 2 elems/thread.
// ---------------------------------------------------------------------------
__global__ void k_softmax(float* __restrict__ out) {
    const int b    = blockIdx.x;
    const int tid  = threadIdx.x;          // 1024 -> 2 elems/thread
    const int lane = tid & 31;
    const int warp = tid >> 5;             // 32 warps
    __shared__ float red[32];

    const float M = dec_f(g_Mbits[b]);
    const float2 e  = ((const float2*)(g_e    + (size_t)b * TT))[tid];
    const float2 hs = ((const float2*)(g_hsum + (size_t)b * TT))[tid];

    const float ex0 = __expf(e.x - M);
    const float ex1 = __expf(e.y - M);
    float sum = ex0 + ex1;
    #pragma unroll
    for (int off = 16; off; off >>= 1)
        sum += __shfl_xor_sync(0xffffffffu, sum, off);
    if (lane == 0) red[warp] = sum;
    __syncthreads();
    float S = 0.f;
    #pragma unroll
    for (int w = 0; w < 32; w++) S += red[w];
    const float inv = 1.f / S;

    float2 o;
    o.x = ex0 * inv * hs.x;
    o.y = ex1 * inv * hs.y;
    ((float2*)(out + (size_t)b * TT))[tid] = o;
}

// ---------------------------------------------------------------------------
extern "C" void kernel_launch(void* const* d_in, const int* in_sizes, int n_in,
                              void* d_out, int out_size) {
    const float* s     = (const float*)d_in[0];   // [64, 512]
    const float* h     = (const float*)d_in[1];   // [64, 2048, 512]
    const float* phi_w = (const float*)d_in[2];   // [512, 512]
    const float* phi_b = (const float*)d_in[3];   // [512]
    const float* psi_w = (const float*)d_in[4];   // [512, 512]
    // d_in[5] = psi_b: unused (softmax shift invariance)
    float* out = (float*)d_out;                   // [64, 2048] fp32

    k_phis<<<dim3(32, 64), 256>>>(s, phi_w, phi_b);
    k_v<<<dim3(32, 4), 512>>>(psi_w);
    k_scores<<<8192, 256>>>(h);    // 8192 * 16 rows = 131072 = BB*TT
    k_softmax<<<64, 1024>>>(out);
}

// round 9
// speedup vs baseline: 1.7152x; 1.7152x over previous
#include <cuda_runtime.h>

#define BB 64
#define TT 2048
#define DD 512

// Scratch (allocation-free contract: __device__ globals)
__device__ float g_phis[BB * DD];
__device__ float g_v[BB * DD];
__device__ float g_e[BB * TT];
__device__ float g_hsum[BB * TT];

// ---------------------------------------------------------------------------
// k_phis: phi_s[b,a] = dot(s[b,:], phi_w[a,:]) + phi_b[a]
// grid (32 a-tiles, 64 b) = 2048 blocks x 256 threads. Each warp does 2 a's.
// ---------------------------------------------------------------------------
__global__ void k_phis(const float* __restrict__ s,
                       const float* __restrict__ phi_w,
                       const float* __restrict__ phi_b) {
    const int b    = blockIdx.y;
    const int tid  = threadIdx.x;          // 256
    const int lane = tid & 31;
    const int warp = tid >> 5;             // 8 warps

    __shared__ float sh_s[DD];
    sh_s[tid]       = s[(size_t)b * DD + tid];
    sh_s[tid + 256] = s[(size_t)b * DD + tid + 256];
    __syncthreads();
    const float4* s4 = (const float4*)sh_s;

    const int a0 = blockIdx.x * 16 + warp * 2;
    const int a1 = a0 + 1;
    const float4* w0 = (const float4*)(phi_w + (size_t)a0 * DD);
    const float4* w1 = (const float4*)(phi_w + (size_t)a1 * DD);

    float acc0 = 0.f, acc1 = 0.f;
    #pragma unroll
    for (int j = 0; j < 4; j++) {
        float4 wa = w0[lane + 32 * j];
        float4 wb = w1[lane + 32 * j];
        float4 sv = s4[lane + 32 * j];
        acc0 += wa.x * sv.x + wa.y * sv.y + wa.z * sv.z + wa.w * sv.w;
        acc1 += wb.x * sv.x + wb.y * sv.y + wb.z * sv.z + wb.w * sv.w;
    }
    #pragma unroll
    for (int off = 16; off; off >>= 1) {
        acc0 += __shfl_xor_sync(0xffffffffu, acc0, off);
        acc1 += __shfl_xor_sync(0xffffffffu, acc1, off);
    }
    if (lane == 0) {
        g_phis[b * DD + a0] = acc0 + phi_b[a0];
        g_phis[b * DD + a1] = acc1 + phi_b[a1];
    }
}

// ---------------------------------------------------------------------------
// k_v: v[b,k] = sum_a phi_s[b,a] * psi_w[a,k]
// grid (32 b-pairs, 4 k-slices) = 128 blocks x 512 threads (16 warps).
// psi_b dropped: softmax is shift-invariant to the per-b constant it adds.
// ---------------------------------------------------------------------------
__global__ void k_v(const float* __restrict__ psi_w) {
    const int b0   = blockIdx.x * 2;
    const int ks   = blockIdx.y;           // k-slice: 32 float4 columns
    const int tid  = threadIdx.x;          // 512
    const int lane = tid & 31;
    const int warp = tid >> 5;             // 16 warps

    __shared__ float  ph0[DD], ph1[DD];
    __shared__ float4 part0[16][32];
    __shared__ float4 part1[16][32];

    ph0[tid] = g_phis[(size_t)b0 * DD + tid];
    ph1[tid] = g_phis[(size_t)(b0 + 1) * DD + tid];
    __syncthreads();

    const float4* w4 = (const float4*)psi_w;     // [512][128] float4
    const int col = ks * 32 + lane;              // 0..127

    float4 acc0 = make_float4(0.f, 0.f, 0.f, 0.f);
    float4 acc1 = make_float4(0.f, 0.f, 0.f, 0.f);
    const int abase = warp * 32;
    #pragma unroll 8
    for (int i = 0; i < 32; i++) {
        const int a = abase + i;
        const float4 w = w4[(size_t)a * 128 + col];
        const float p0 = ph0[a], p1 = ph1[a];
        acc0.x += p0 * w.x; acc0.y += p0 * w.y;
        acc0.z += p0 * w.z; acc0.w += p0 * w.w;
        acc1.x += p1 * w.x; acc1.y += p1 * w.y;
        acc1.z += p1 * w.z; acc1.w += p1 * w.w;
    }
    part0[warp][lane] = acc0;
    part1[warp][lane] = acc1;
    __syncthreads();

    if (warp == 0) {
        float4 r = part0[0][lane];
        #pragma unroll
        for (int w = 1; w < 16; w++) {
            float4 p = part0[w][lane];
            r.x += p.x; r.y += p.y; r.z += p.z; r.w += p.w;
        }
        ((float4*)g_v)[(size_t)b0 * 128 + col] = r;
    } else if (warp == 1) {
        float4 r = part1[0][lane];
        #pragma unroll
        for (int w = 1; w < 16; w++) {
            float4 p = part1[w][lane];
            r.x += p.x; r.y += p.y; r.z += p.z; r.w += p.w;
        }
        ((float4*)g_v)[(size_t)(b0 + 1) * 128 + col] = r;
    }
}

// ---------------------------------------------------------------------------
// k_scores: the DRAM-bound pass (one 268 MB streaming read of h).
// EXACT round-7 structure (best measured: 59.9us total) with ONE isolated
// change: h loads use __ldcs (evict-first; h has zero reuse).
// grid 8192 x 256, __launch_bounds__(256,4): 4 CTAs/SM = 32 warps/SM.
// v staged via smem once per block, pinned in 16 regs/warp.
// NO atomics (round-8 proved per-b atomic fan-in costs ~35us).
// ---------------------------------------------------------------------------
__global__ void __launch_bounds__(256, 4) k_scores(const float* __restrict__ h) {
    const int tid  = threadIdx.x;
    const int lane = tid & 31;
    const int warp = tid >> 5;
    const int row0 = blockIdx.x * 16 + warp * 2;
    const int b    = blockIdx.x >> 7;      // 128 blocks per b

    __shared__ float sh_v[DD];
    ((float2*)sh_v)[tid] = ((const float2*)(g_v + (size_t)b * DD))[tid];
    __syncthreads();

    const float4* sv4 = (const float4*)sh_v;
    float4 v[4];
    #pragma unroll
    for (int j = 0; j < 4; j++) v[j] = sv4[lane + 32 * j];

    const float4* ha = (const float4*)(h + (size_t)row0 * DD);
    const float4* hb = ha + 128;
    float4 A[4], B[4];
    #pragma unroll
    for (int j = 0; j < 4; j++) A[j] = __ldcs(&ha[lane + 32 * j]);
    #pragma unroll
    for (int j = 0; j < 4; j++) B[j] = __ldcs(&hb[lane + 32 * j]);

    float e0 = 0.f, s0 = 0.f, e1 = 0.f, s1 = 0.f;
    #pragma unroll
    for (int j = 0; j < 4; j++) {
        e0 += A[j].x * v[j].x + A[j].y * v[j].y + A[j].z * v[j].z + A[j].w * v[j].w;
        s0 += (A[j].x + A[j].y) + (A[j].z + A[j].w);
        e1 += B[j].x * v[j].x + B[j].y * v[j].y + B[j].z * v[j].z + B[j].w * v[j].w;
        s1 += (B[j].x + B[j].y) + (B[j].z + B[j].w);
    }
    #pragma unroll
    for (int off = 16; off; off >>= 1) {
        e0 += __shfl_xor_sync(0xffffffffu, e0, off);
        s0 += __shfl_xor_sync(0xffffffffu, s0, off);
        e1 += __shfl_xor_sync(0xffffffffu, e1, off);
        s1 += __shfl_xor_sync(0xffffffffu, s1, off);
    }
    if (lane == 0) {
        *(float2*)(g_e    + row0) = make_float2(e0, e1);
        *(float2*)(g_hsum + row0) = make_float2(s0, s1);
    }
}

// ---------------------------------------------------------------------------
// k_softmax: per-b softmax over T=2048 + output c = alpha * hsum.
// EXACT round-7 version: 64 blocks x 1024 threads (2 e/thread), hsum loaded
// up front so its latency overlaps both block reductions.
// ---------------------------------------------------------------------------
__global__ void k_softmax(float* __restrict__ out) {
    const int b    = blockIdx.x;
    const int tid  = threadIdx.x;          // 1024 -> 2 elems/thread
    const int lane = tid & 31;
    const int warp = tid >> 5;             // 32 warps
    __shared__ float red[32];

    const float2 e  = ((const float2*)(g_e    + (size_t)b * TT))[tid];
    const float2 hs = ((const float2*)(g_hsum + (size_t)b * TT))[tid];

    float m = fmaxf(e.x, e.y);
    #pragma unroll
    for (int off = 16; off; off >>= 1)
        m = fmaxf(m, __shfl_xor_sync(0xffffffffu, m, off));
    if (lane == 0) red[warp] = m;
    __syncthreads();
    float M = red[0];
    #pragma unroll
    for (int w = 1; w < 32; w++) M = fmaxf(M, red[w]);
    __syncthreads();

    const float ex0 = __expf(e.x - M);
    const float ex1 = __expf(e.y - M);
    float sum = ex0 + ex1;
    #pragma unroll
    for (int off = 16; off; off >>= 1)
        sum += __shfl_xor_sync(0xffffffffu, sum, off);
    if (lane == 0) red[warp] = sum;
    __syncthreads();
    float S = 0.f;
    #pragma unroll
    for (int w = 0; w < 32; w++) S += red[w];
    const float inv = 1.f / S;

    float2 o;
    o.x = ex0 * inv * hs.x;
    o.y = ex1 * inv * hs.y;
    ((float2*)(out + (size_t)b * TT))[tid] = o;
}

// ---------------------------------------------------------------------------
extern "C" void kernel_launch(void* const* d_in, const int* in_sizes, int n_in,
                              void* d_out, int out_size) {
    const float* s     = (const float*)d_in[0];   // [64, 512]
    const float* h     = (const float*)d_in[1];   // [64, 2048, 512]
    const float* phi_w = (const float*)d_in[2];   // [512, 512]
    const float* phi_b = (const float*)d_in[3];   // [512]
    const float* psi_w = (const float*)d_in[4];   // [512, 512]
    // d_in[5] = psi_b: unused (softmax shift invariance)
    float* out = (float*)d_out;                   // [64, 2048] fp32

    k_phis<<<dim3(32, 64), 256>>>(s, phi_w, phi_b);
    k_v<<<dim3(32, 4), 512>>>(psi_w);
    k_scores<<<8192, 256>>>(h);    // 8192 * 16 rows = 131072 = BB*TT
    k_softmax<<<64, 1024>>>(out);
}